// round 1
// baseline (speedup 1.0000x reference)
#include <cuda_runtime.h>
#include <math.h>

// ---------------- problem constants ----------------
#define NB    4
#define NL    1024
#define HID   2048
#define NH    16
#define DK    128
#define DV    128
#define KEYD  2048          // H*DK
#define VALD  2048          // H*DV
#define CONVD 6144          // 2*KEYD + VALD
#define QKVZN 8192          // 2*KEYD + 2*VALD
#define ML    4096          // B*L

// ---------------- device scratch (static, no allocs) ----------------
__device__ float g_qkvz[(size_t)ML * QKVZN];   // 128 MiB
__device__ float g_ba[ML * 32];
__device__ float g_x[(size_t)ML * CONVD];      // conv out; q,k l2-normed in place
__device__ float g_g[ML * NH];
__device__ float g_beta[ML * NH];
__device__ float g_o[(size_t)ML * VALD];       // scan out, gated in place

// ====================================================================
// Generic fp32 SGEMM: C[M,N] = A[M,K] @ B[K,N], row-major.
// 128x128 block tile, BK=8, 8x8 per thread, 256 threads, double-buffered smem.
// Requires M%128==0, N%128==0, K%8==0.
// ====================================================================
__global__ void __launch_bounds__(256) sgemm128(const float* __restrict__ A,
                                                const float* __restrict__ B,
                                                float* __restrict__ C,
                                                int M, int N, int K)
{
    __shared__ float As[2][8][128];
    __shared__ float Bs[2][8][128];

    const int tid = threadIdx.x;
    const int m0 = blockIdx.y * 128;
    const int n0 = blockIdx.x * 128;

    const int arow = tid >> 1;            // 0..127
    const int acol = (tid & 1) * 4;       // 0 or 4
    const int brow = tid >> 5;            // 0..7
    const int bcol = (tid & 31) * 4;      // 0..124

    const float* Aptr = A + (size_t)(m0 + arow) * K + acol;
    const float* Bptr = B + (size_t)brow * N + n0 + bcol;

    const int ty = tid >> 4;   // 0..15
    const int tx = tid & 15;   // 0..15

    float acc[8][8];
#pragma unroll
    for (int i = 0; i < 8; i++)
#pragma unroll
        for (int j = 0; j < 8; j++) acc[i][j] = 0.f;

    // prologue: stage tile 0
    float4 a4 = *(const float4*)Aptr;
    float4 b4 = *(const float4*)Bptr;
    As[0][acol + 0][arow] = a4.x;
    As[0][acol + 1][arow] = a4.y;
    As[0][acol + 2][arow] = a4.z;
    As[0][acol + 3][arow] = a4.w;
    *(float4*)&Bs[0][brow][bcol] = b4;
    __syncthreads();

    const int ntiles = K >> 3;
    for (int kt = 0; kt < ntiles; kt++) {
        const int cur = kt & 1;
        if (kt + 1 < ntiles) {
            a4 = *(const float4*)(Aptr + (kt + 1) * 8);
            b4 = *(const float4*)(Bptr + (size_t)(kt + 1) * 8 * N);
        }
#pragma unroll
        for (int k = 0; k < 8; k++) {
            float ar[8], br[8];
            *(float4*)&ar[0] = *(float4*)&As[cur][k][ty * 8];
            *(float4*)&ar[4] = *(float4*)&As[cur][k][ty * 8 + 4];
            *(float4*)&br[0] = *(float4*)&Bs[cur][k][tx * 8];
            *(float4*)&br[4] = *(float4*)&Bs[cur][k][tx * 8 + 4];
#pragma unroll
            for (int i = 0; i < 8; i++)
#pragma unroll
                for (int j = 0; j < 8; j++)
                    acc[i][j] += ar[i] * br[j];
        }
        if (kt + 1 < ntiles) {
            const int nxt = cur ^ 1;
            As[nxt][acol + 0][arow] = a4.x;
            As[nxt][acol + 1][arow] = a4.y;
            As[nxt][acol + 2][arow] = a4.z;
            As[nxt][acol + 3][arow] = a4.w;
            *(float4*)&Bs[nxt][brow][bcol] = b4;
        }
        __syncthreads();
    }

#pragma unroll
    for (int i = 0; i < 8; i++) {
        float* cp = C + (size_t)(m0 + ty * 8 + i) * N + n0 + tx * 8;
        *(float4*)cp       = make_float4(acc[i][0], acc[i][1], acc[i][2], acc[i][3]);
        *(float4*)(cp + 4) = make_float4(acc[i][4], acc[i][5], acc[i][6], acc[i][7]);
    }
}

// ====================================================================
// Small GEMM: ba[4096,32] = hidden[4096,2048] @ W_ba[2048,32]
// One warp per output row; lane j owns column j.
// ====================================================================
__global__ void __launch_bounds__(256) ba_gemm_kernel(const float* __restrict__ A,
                                                      const float* __restrict__ Bm,
                                                      float* __restrict__ C)
{
    const int row  = blockIdx.x * 8 + (threadIdx.x >> 5);
    const int lane = threadIdx.x & 31;
    const float* a = A + (size_t)row * HID;
    float acc = 0.f;
#pragma unroll 4
    for (int k = 0; k < HID; k += 4) {
        float4 av = *(const float4*)&a[k];   // lane-uniform broadcast
        acc += av.x * Bm[(k + 0) * 32 + lane];
        acc += av.y * Bm[(k + 1) * 32 + lane];
        acc += av.z * Bm[(k + 2) * 32 + lane];
        acc += av.w * Bm[(k + 3) * 32 + lane];
    }
    C[row * 32 + lane] = acc;
}

// ====================================================================
// Fused depthwise causal conv1d (KS=4) + per-head l2norm of q,k
// + g/beta computation. One block per (b,l).
// ====================================================================
__global__ void __launch_bounds__(256) conv_norm_kernel(const float* __restrict__ qkvz,
                                                        const float* __restrict__ ba,
                                                        const float* __restrict__ conv_w,
                                                        const float* __restrict__ conv_b,
                                                        const float* __restrict__ A_log,
                                                        const float* __restrict__ dt_bias,
                                                        float* __restrict__ x_out,
                                                        float* __restrict__ g_out,
                                                        float* __restrict__ beta_out)
{
    const int bl = blockIdx.x;
    const int b  = bl >> 10;
    const int l  = bl & 1023;

    __shared__ float xs[CONVD];

    for (int c = threadIdx.x; c < CONVD; c += 256) {
        float acc = conv_b[c];
#pragma unroll
        for (int j = 0; j < 4; j++) {
            const int ll = l - 3 + j;
            if (ll >= 0)
                acc += qkvz[((size_t)(b * NL + ll)) * QKVZN + c] * conv_w[c * 4 + j];
        }
        xs[c] = acc;
    }
    __syncthreads();

    // l2norm over 32 head-chunks of 128 (q heads 0..15, k heads 16..31)
    const int warp = threadIdx.x >> 5;
    const int lane = threadIdx.x & 31;
    for (int hh = warp; hh < 32; hh += 8) {
        const int base = hh * 128;
        float ss = 0.f;
#pragma unroll
        for (int i = 0; i < 4; i++) {
            float v = xs[base + lane + 32 * i];
            ss += v * v;
        }
#pragma unroll
        for (int off = 16; off; off >>= 1) ss += __shfl_xor_sync(0xffffffffu, ss, off);
        const float rn = rsqrtf(ss + 1e-6f);
#pragma unroll
        for (int i = 0; i < 4; i++) xs[base + lane + 32 * i] *= rn;
    }
    __syncthreads();

    for (int c = threadIdx.x; c < CONVD; c += 256)
        x_out[(size_t)bl * CONVD + c] = xs[c];

    if (threadIdx.x < NH) {
        const int h = threadIdx.x;
        const float bb = ba[bl * 32 + h];
        const float aa = ba[bl * 32 + NH + h];
        const float beta = 1.f / (1.f + expf(-bb));
        const float s = aa + dt_bias[h];
        const float sp = (s > 20.f) ? s : log1pf(expf(s));
        g_out[bl * NH + h]    = -expf(A_log[h]) * sp;
        beta_out[bl * NH + h] = beta;
    }
}

// ====================================================================
// Gated delta-rule scan. Grid = 64 (b,h) x 2 (d-halves) = 128 blocks.
// 256 threads: column d = half*64 + (tid>>2), sub = tid&3 owns kk = 4i+sub.
// State S[:,d] lives in registers (32 floats/thread). k,q,v,g,beta staged
// through double-buffered smem with next-step global prefetch.
// ====================================================================
__global__ void __launch_bounds__(256) scan_kernel(const float* __restrict__ x,
                                                   const float* __restrict__ gg,
                                                   const float* __restrict__ bb,
                                                   float* __restrict__ o)
{
    const int blk  = blockIdx.x;      // 0..127
    const int bh   = blk >> 1;        // 0..63
    const int half = blk & 1;
    const int b = bh >> 4, h = bh & 15;
    const int tid = threadIdx.x;
    const int col = tid >> 2;         // 0..63
    const int sub = tid & 3;
    const int d   = half * 64 + col;

    __shared__ float k_s[2][128];
    __shared__ float q_s[2][128];
    __shared__ float v_s[2][64];
    __shared__ float gb_s[2][2];

    float s[32];
#pragma unroll
    for (int i = 0; i < 32; i++) s[i] = 0.f;

    const size_t xbase = (size_t)b * NL * CONVD;

    // ---- loader: each thread fetches <=2 values per step ----
    float r0 = 0.f, r1 = 0.f;
    {
        const size_t row = xbase;
        if (tid < 128) r0 = x[row + KEYD + h * 128 + tid];                 // k
        else           r0 = x[row + h * 128 + (tid - 128)];                // q
        if (tid < 64)       r1 = x[row + 2 * KEYD + h * 128 + half * 64 + tid]; // v
        else if (tid == 64) r1 = gg[(b * NL) * NH + h];
        else if (tid == 65) r1 = bb[(b * NL) * NH + h];
    }
    if (tid < 128) k_s[0][tid] = r0; else q_s[0][tid - 128] = r0;
    if (tid < 64)       v_s[0][tid]  = r1;
    else if (tid == 64) gb_s[0][0]   = r1;
    else if (tid == 65) gb_s[0][1]   = r1;
    __syncthreads();

    const float scale = 0.08838834764831845f;  // DK^-0.5
    float* obase = o + (size_t)b * NL * VALD + h * 128 + d;

    for (int l = 0; l < NL; l++) {
        const int cur = l & 1;
        const float eg   = expf(gb_s[cur][0]);
        const float beta = gb_s[cur][1];
        const float vv   = v_s[cur][col];
        float kr[32];
#pragma unroll
        for (int i = 0; i < 32; i++) kr[i] = k_s[cur][i * 4 + sub];

        // prefetch next step (global -> regs), overlapped with compute
        if (l + 1 < NL) {
            const size_t row = xbase + (size_t)(l + 1) * CONVD;
            if (tid < 128) r0 = x[row + KEYD + h * 128 + tid];
            else           r0 = x[row + h * 128 + (tid - 128)];
            if (tid < 64)       r1 = x[row + 2 * KEYD + h * 128 + half * 64 + tid];
            else if (tid == 64) r1 = gg[(b * NL + l + 1) * NH + h];
            else if (tid == 65) r1 = bb[(b * NL + l + 1) * NH + h];
        }

        // decay + v_pred partial
        float vp = 0.f;
#pragma unroll
        for (int i = 0; i < 32; i++) {
            s[i] *= eg;
            vp += kr[i] * s[i];
        }
        vp += __shfl_xor_sync(0xffffffffu, vp, 1);
        vp += __shfl_xor_sync(0xffffffffu, vp, 2);
        const float delta = (vv - vp) * beta;

        // rank-1 update + output partial
        float oo = 0.f;
#pragma unroll
        for (int i = 0; i < 32; i++) {
            s[i] += kr[i] * delta;
            oo += q_s[cur][i * 4 + sub] * s[i];
        }
        oo += __shfl_xor_sync(0xffffffffu, oo, 1);
        oo += __shfl_xor_sync(0xffffffffu, oo, 2);
        if (sub == 0) obase[(size_t)l * VALD] = oo * scale;

        // stage prefetched data into the other buffer
        if (l + 1 < NL) {
            const int nxt = cur ^ 1;
            if (tid < 128) k_s[nxt][tid] = r0; else q_s[nxt][tid - 128] = r0;
            if (tid < 64)       v_s[nxt][tid] = r1;
            else if (tid == 64) gb_s[nxt][0]  = r1;
            else if (tid == 65) gb_s[nxt][1]  = r1;
        }
        __syncthreads();
    }
}

// ====================================================================
// RMS-norm over DV per (b,l,h), * norm_w * sigmoid(z). One warp per (bl,h).
// In-place on o.
// ====================================================================
__global__ void __launch_bounds__(256) gate_norm_kernel(const float* __restrict__ qkvz,
                                                        const float* __restrict__ norm_w,
                                                        float* __restrict__ o)
{
    const int gid  = blockIdx.x * 256 + threadIdx.x;
    const int wid  = gid >> 5;        // 0..65535
    const int lane = gid & 31;
    const int bl = wid >> 4;
    const int h  = wid & 15;

    float* op = o + (size_t)bl * VALD + h * 128 + lane * 4;
    float4 ov = *(float4*)op;
    float ss = ov.x * ov.x + ov.y * ov.y + ov.z * ov.z + ov.w * ov.w;
#pragma unroll
    for (int off = 16; off; off >>= 1) ss += __shfl_xor_sync(0xffffffffu, ss, off);
    const float rs = rsqrtf(ss * (1.f / 128.f) + 1e-6f);

    const float4 z = *(const float4*)&qkvz[(size_t)bl * QKVZN + CONVD + h * 128 + lane * 4];
    const float4 w = *(const float4*)&norm_w[lane * 4];
    ov.x = ov.x * rs * w.x * (1.f / (1.f + expf(-z.x)));
    ov.y = ov.y * rs * w.y * (1.f / (1.f + expf(-z.y)));
    ov.z = ov.z * rs * w.z * (1.f / (1.f + expf(-z.z)));
    ov.w = ov.w * rs * w.w * (1.f / (1.f + expf(-z.w)));
    *(float4*)op = ov;
}

// ====================================================================
extern "C" void kernel_launch(void* const* d_in, const int* in_sizes, int n_in,
                              void* d_out, int out_size)
{
    const float* hidden  = (const float*)d_in[0];
    const float* W_qkvz  = (const float*)d_in[1];
    const float* W_ba    = (const float*)d_in[2];
    const float* conv_w  = (const float*)d_in[3];
    const float* conv_b  = (const float*)d_in[4];
    const float* A_log   = (const float*)d_in[5];
    const float* dt_bias = (const float*)d_in[6];
    const float* norm_w  = (const float*)d_in[7];
    const float* W_out   = (const float*)d_in[8];
    float* out = (float*)d_out;

    float *qkvz, *ba, *xbuf, *gbuf, *betabuf, *obuf;
    cudaGetSymbolAddress((void**)&qkvz,    g_qkvz);
    cudaGetSymbolAddress((void**)&ba,      g_ba);
    cudaGetSymbolAddress((void**)&xbuf,    g_x);
    cudaGetSymbolAddress((void**)&gbuf,    g_g);
    cudaGetSymbolAddress((void**)&betabuf, g_beta);
    cudaGetSymbolAddress((void**)&obuf,    g_o);

    // 1. qkvz = hidden @ W_qkvz   [4096, 8192]
    sgemm128<<<dim3(QKVZN / 128, ML / 128), 256>>>(hidden, W_qkvz, qkvz, ML, QKVZN, HID);
    // 2. ba = hidden @ W_ba       [4096, 32]
    ba_gemm_kernel<<<ML / 8, 256>>>(hidden, W_ba, ba);
    // 3. conv + l2norm + g/beta
    conv_norm_kernel<<<ML, 256>>>(qkvz, ba, conv_w, conv_b, A_log, dt_bias,
                                  xbuf, gbuf, betabuf);
    // 4. gated delta scan
    scan_kernel<<<128, 256>>>(xbuf, gbuf, betabuf, obuf);
    // 5. RMS norm + sigmoid(z) gate
    gate_norm_kernel<<<(ML * NH * 32) / 256, 256>>>(qkvz, norm_w, obuf);
    // 6. out = o @ W_out          [4096, 2048]
    sgemm128<<<dim3(HID / 128, ML / 128), 256>>>(obuf, W_out, out, ML, HID, HID);
}

// round 3
// speedup vs baseline: 1.9268x; 1.9268x over previous
#include <cuda_runtime.h>
#include <cuda_bf16.h>
#include <math.h>
#include <stdint.h>

// ---------------- problem constants ----------------
#define NB    4
#define NL    1024
#define HID   2048
#define NH    16
#define DK    128
#define DV    128
#define KEYD  2048          // H*DK
#define VALD  2048          // H*DV
#define CONVD 6144          // 2*KEYD + VALD
#define QKVZN 8192          // 2*KEYD + 2*VALD
#define ML    4096          // B*L

// ---------------- device scratch (static, no allocs) ----------------
__device__ float g_qkvz[(size_t)ML * QKVZN];   // 128 MiB
__device__ float g_ba[ML * 32];
__device__ float g_x[(size_t)ML * CONVD];
__device__ float g_g[ML * NH];
__device__ float g_beta[ML * NH];
__device__ float g_o[(size_t)ML * VALD];

// bf16 hi/lo split operands
__device__ __nv_bfloat16 g_hh[(size_t)ML * HID];
__device__ __nv_bfloat16 g_hl[(size_t)ML * HID];
__device__ __nv_bfloat16 g_wqh[(size_t)QKVZN * HID];   // W_qkvz^T  [N,K]
__device__ __nv_bfloat16 g_wql[(size_t)QKVZN * HID];
__device__ __nv_bfloat16 g_woh[(size_t)HID * VALD];    // W_out^T   [N,K]
__device__ __nv_bfloat16 g_wol[(size_t)HID * VALD];
__device__ __nv_bfloat16 g_oh[(size_t)ML * VALD];
__device__ __nv_bfloat16 g_ol[(size_t)ML * VALD];

// ==================== PTX helpers (base compute_103 safe) ====================
__device__ __forceinline__ uint32_t smem_u32(const void* p) {
    uint32_t a;
    asm("{ .reg .u64 t; cvta.to.shared.u64 t, %1; cvt.u32.u64 %0, t; }" : "=r"(a) : "l"(p));
    return a;
}
__device__ __forceinline__ void cp16(uint32_t dst, const void* src) {
    asm volatile("cp.async.cg.shared.global [%0], [%1], 16;" :: "r"(dst), "l"(src));
}
__device__ __forceinline__ void cp_commit() {
    asm volatile("cp.async.commit_group;" ::: "memory");
}
__device__ __forceinline__ void cp_wait0() {
    asm volatile("cp.async.wait_group 0;" ::: "memory");
}
__device__ __forceinline__ void ldsm4(uint32_t* r, uint32_t addr) {
    asm volatile("ldmatrix.sync.aligned.m8n8.x4.shared.b16 {%0,%1,%2,%3}, [%4];"
                 : "=r"(r[0]), "=r"(r[1]), "=r"(r[2]), "=r"(r[3]) : "r"(addr));
}
__device__ __forceinline__ void mma16816(float* c, const uint32_t* a, const uint32_t* b) {
    asm volatile("mma.sync.aligned.m16n8k16.row.col.f32.bf16.bf16.f32 "
                 "{%0,%1,%2,%3}, {%4,%5,%6,%7}, {%8,%9}, {%0,%1,%2,%3};"
                 : "+f"(c[0]), "+f"(c[1]), "+f"(c[2]), "+f"(c[3])
                 : "r"(a[0]), "r"(a[1]), "r"(a[2]), "r"(a[3]), "r"(b[0]), "r"(b[1]));
}
__device__ __forceinline__ uint32_t sw128(uint32_t off) {
    return off ^ ((off >> 3) & 0x70);
}

// ==================== mma.sync bf16 GEMM (3-product hi/lo split) =============
// C[M,N] = (Ah+Al)[M,K] @ (Bh+Bl)^T ; B arrays stored [N,K] row-major.
// Block 128x128, BK=64 bf16 (128B rows, SW128 swizzle), double-buffered cp.async.
// 8 warps = 2(M) x 4(N); warp tile 64x32 -> 4 m16-tiles x 4 n8-tiles.
#define BM 128
#define BN 128
#define BKC 64
#define TILE_B 16384                      // one 128x64 bf16 tile
#define BUF_B (4 * TILE_B)                // Ah, Al, Bh, Bl
#define GEMM_SMEM (2 * BUF_B)             // 128 KiB

__device__ __forceinline__ void gemm_load_chunk(
    const __nv_bfloat16* Ah, const __nv_bfloat16* Al,
    const __nv_bfloat16* Bh, const __nv_bfloat16* Bl,
    int Kdim, int k0, uint32_t sbuf, int tid)
{
    // each tile: 128 rows x 128 bytes = 1024 x 16B units; 256 threads -> 4 iters
#pragma unroll
    for (int it = 0; it < 4; it++) {
        const int u   = it * 256 + tid;
        const int row = u >> 3;
        const int cb  = (u & 7) << 4;
        const uint32_t so = sw128((uint32_t)(row * 128 + cb));
        const size_t go = (size_t)row * Kdim + k0;   // elements
        cp16(sbuf + 0 * TILE_B + so, (const char*)(Ah + go) + cb);
        cp16(sbuf + 1 * TILE_B + so, (const char*)(Al + go) + cb);
        cp16(sbuf + 2 * TILE_B + so, (const char*)(Bh + go) + cb);
        cp16(sbuf + 3 * TILE_B + so, (const char*)(Bl + go) + cb);
    }
}

__global__ void __launch_bounds__(256, 1) mma_gemm(
    const __nv_bfloat16* __restrict__ Ah, const __nv_bfloat16* __restrict__ Al,
    const __nv_bfloat16* __restrict__ Bh, const __nv_bfloat16* __restrict__ Bl,
    float* __restrict__ C, int Kdim, int Nout)
{
    extern __shared__ __align__(1024) char smem[];
    const uint32_t sbase = smem_u32(smem);
    const int tid  = threadIdx.x;
    const int wid  = tid >> 5;
    const int lane = tid & 31;
    const int wm = wid >> 2;          // 0..1
    const int wn = wid & 3;           // 0..3
    const int m0 = blockIdx.y * BM;
    const int n0 = blockIdx.x * BN;

    const __nv_bfloat16* Ahb = Ah + (size_t)m0 * Kdim;
    const __nv_bfloat16* Alb = Al + (size_t)m0 * Kdim;
    const __nv_bfloat16* Bhb = Bh + (size_t)n0 * Kdim;
    const __nv_bfloat16* Blb = Bl + (size_t)n0 * Kdim;

    float acc[4][4][4];
#pragma unroll
    for (int i = 0; i < 4; i++)
#pragma unroll
        for (int j = 0; j < 4; j++)
#pragma unroll
            for (int r = 0; r < 4; r++) acc[i][j][r] = 0.f;

    // precomputed ldmatrix relative offsets (within a tile)
    const uint32_t a_off0 = (uint32_t)((wm * 64 + (lane & 15)) * 128 + ((lane >> 4) << 4));
    const uint32_t b_off0 = (uint32_t)((wn * 32 + (lane & 7) + ((lane >> 4) << 3)) * 128
                                       + (((lane >> 3) & 1) << 4));

    gemm_load_chunk(Ahb, Alb, Bhb, Blb, Kdim, 0, sbase, tid);
    cp_commit();

    const int nchunks = Kdim / BKC;
    for (int c = 0; c < nchunks; c++) {
        const uint32_t buf = sbase + (uint32_t)(c & 1) * BUF_B;
        cp_wait0();
        __syncthreads();
        if (c + 1 < nchunks) {
            gemm_load_chunk(Ahb, Alb, Bhb, Blb, Kdim, (c + 1) * BKC,
                            sbase + (uint32_t)((c + 1) & 1) * BUF_B, tid);
            cp_commit();
        }

        const uint32_t aHi = buf + 0 * TILE_B, aLo = buf + 1 * TILE_B;
        const uint32_t bHi = buf + 2 * TILE_B, bLo = buf + 3 * TILE_B;
#pragma unroll
        for (int k16 = 0; k16 < 4; k16++) {
            uint32_t ah[4][4], al[4][4], bh[2][4], bl[2][4];
#pragma unroll
            for (int mt = 0; mt < 4; mt++) {
                const uint32_t off = sw128(a_off0 + (uint32_t)(mt * 16 * 128 + k16 * 32));
                ldsm4(ah[mt], aHi + off);
                ldsm4(al[mt], aLo + off);
            }
#pragma unroll
            for (int p = 0; p < 2; p++) {
                const uint32_t off = sw128(b_off0 + (uint32_t)(p * 16 * 128 + k16 * 32));
                ldsm4(bh[p], bHi + off);
                ldsm4(bl[p], bLo + off);
            }
#pragma unroll
            for (int mt = 0; mt < 4; mt++) {
#pragma unroll
                for (int nt = 0; nt < 4; nt++) {
                    const uint32_t* bhp = &bh[nt >> 1][(nt & 1) * 2];
                    const uint32_t* blp = &bl[nt >> 1][(nt & 1) * 2];
                    mma16816(acc[mt][nt], ah[mt], bhp);
                    mma16816(acc[mt][nt], ah[mt], blp);
                    mma16816(acc[mt][nt], al[mt], bhp);
                }
            }
        }
        __syncthreads();
    }

    // epilogue
    const int rbase = m0 + wm * 64 + (lane >> 2);
    const int cbase = n0 + wn * 32 + (lane & 3) * 2;
#pragma unroll
    for (int mt = 0; mt < 4; mt++) {
#pragma unroll
        for (int nt = 0; nt < 4; nt++) {
            float* p0 = C + (size_t)(rbase + mt * 16) * Nout + cbase + nt * 8;
            float* p1 = p0 + 8 * Nout;
            *(float2*)p0 = make_float2(acc[mt][nt][0], acc[mt][nt][1]);
            *(float2*)p1 = make_float2(acc[mt][nt][2], acc[mt][nt][3]);
        }
    }
}

// ==================== fp32 -> bf16 hi/lo split ====================
__global__ void __launch_bounds__(256) split_kernel(const float* __restrict__ s,
                                                    __nv_bfloat16* __restrict__ hi,
                                                    __nv_bfloat16* __restrict__ lo,
                                                    int n4)
{
    const int i = blockIdx.x * 256 + threadIdx.x;
    if (i >= n4) return;
    float4 v = ((const float4*)s)[i];
    __nv_bfloat16 h0 = __float2bfloat16_rn(v.x);
    __nv_bfloat16 h1 = __float2bfloat16_rn(v.y);
    __nv_bfloat16 h2 = __float2bfloat16_rn(v.z);
    __nv_bfloat16 h3 = __float2bfloat16_rn(v.w);
    __nv_bfloat16 l0 = __float2bfloat16_rn(v.x - __bfloat162float(h0));
    __nv_bfloat16 l1 = __float2bfloat16_rn(v.y - __bfloat162float(h1));
    __nv_bfloat16 l2 = __float2bfloat16_rn(v.z - __bfloat162float(h2));
    __nv_bfloat16 l3 = __float2bfloat16_rn(v.w - __bfloat162float(h3));
    __nv_bfloat162* hp = (__nv_bfloat162*)(hi + (size_t)i * 4);
    __nv_bfloat162* lp = (__nv_bfloat162*)(lo + (size_t)i * 4);
    hp[0] = __nv_bfloat162(h0, h1); hp[1] = __nv_bfloat162(h2, h3);
    lp[0] = __nv_bfloat162(l0, l1); lp[1] = __nv_bfloat162(l2, l3);
}

// transpose + split: src[K,N] f32 -> hi/lo [N,K] bf16
__global__ void __launch_bounds__(256) tsplit_kernel(const float* __restrict__ src,
                                                     __nv_bfloat16* __restrict__ hi,
                                                     __nv_bfloat16* __restrict__ lo,
                                                     int K, int N)
{
    __shared__ float t[32][33];
    const int n0 = blockIdx.x * 32;
    const int k0 = blockIdx.y * 32;
    for (int j = threadIdx.y; j < 32; j += 8)
        t[j][threadIdx.x] = src[(size_t)(k0 + j) * N + n0 + threadIdx.x];
    __syncthreads();
    for (int j = threadIdx.y; j < 32; j += 8) {
        const float x = t[threadIdx.x][j];
        const __nv_bfloat16 h = __float2bfloat16_rn(x);
        const size_t oi = (size_t)(n0 + j) * K + k0 + threadIdx.x;
        hi[oi] = h;
        lo[oi] = __float2bfloat16_rn(x - __bfloat162float(h));
    }
}

// ==================== small GEMM: ba ====================
__global__ void __launch_bounds__(256) ba_gemm_kernel(const float* __restrict__ A,
                                                      const float* __restrict__ Bm,
                                                      float* __restrict__ C)
{
    const int row  = blockIdx.x * 8 + (threadIdx.x >> 5);
    const int lane = threadIdx.x & 31;
    const float* a = A + (size_t)row * HID;
    float acc = 0.f;
#pragma unroll 4
    for (int k = 0; k < HID; k += 4) {
        float4 av = *(const float4*)&a[k];
        acc += av.x * Bm[(k + 0) * 32 + lane];
        acc += av.y * Bm[(k + 1) * 32 + lane];
        acc += av.z * Bm[(k + 2) * 32 + lane];
        acc += av.w * Bm[(k + 3) * 32 + lane];
    }
    C[row * 32 + lane] = acc;
}

// ==================== conv + l2norm + g/beta ====================
__global__ void __launch_bounds__(256) conv_norm_kernel(const float* __restrict__ qkvz,
                                                        const float* __restrict__ ba,
                                                        const float* __restrict__ conv_w,
                                                        const float* __restrict__ conv_b,
                                                        const float* __restrict__ A_log,
                                                        const float* __restrict__ dt_bias,
                                                        float* __restrict__ x_out,
                                                        float* __restrict__ g_out,
                                                        float* __restrict__ beta_out)
{
    const int bl = blockIdx.x;
    const int b  = bl >> 10;
    const int l  = bl & 1023;

    __shared__ float xs[CONVD];

    for (int c = threadIdx.x; c < CONVD; c += 256) {
        float acc = conv_b[c];
#pragma unroll
        for (int j = 0; j < 4; j++) {
            const int ll = l - 3 + j;
            if (ll >= 0)
                acc += qkvz[((size_t)(b * NL + ll)) * QKVZN + c] * conv_w[c * 4 + j];
        }
        xs[c] = acc;
    }
    __syncthreads();

    const int warp = threadIdx.x >> 5;
    const int lane = threadIdx.x & 31;
    for (int hh = warp; hh < 32; hh += 8) {
        const int base = hh * 128;
        float ss = 0.f;
#pragma unroll
        for (int i = 0; i < 4; i++) {
            float v = xs[base + lane + 32 * i];
            ss += v * v;
        }
#pragma unroll
        for (int off = 16; off; off >>= 1) ss += __shfl_xor_sync(0xffffffffu, ss, off);
        const float rn = rsqrtf(ss + 1e-6f);
#pragma unroll
        for (int i = 0; i < 4; i++) xs[base + lane + 32 * i] *= rn;
    }
    __syncthreads();

    for (int c = threadIdx.x; c < CONVD; c += 256)
        x_out[(size_t)bl * CONVD + c] = xs[c];

    if (threadIdx.x < NH) {
        const int h = threadIdx.x;
        const float bb = ba[bl * 32 + h];
        const float aa = ba[bl * 32 + NH + h];
        const float beta = 1.f / (1.f + expf(-bb));
        const float s = aa + dt_bias[h];
        const float sp = (s > 20.f) ? s : log1pf(expf(s));
        g_out[bl * NH + h]    = -expf(A_log[h]) * sp;
        beta_out[bl * NH + h] = beta;
    }
}

// ==================== gated delta-rule scan ====================
__global__ void __launch_bounds__(256) scan_kernel(const float* __restrict__ x,
                                                   const float* __restrict__ gg,
                                                   const float* __restrict__ bb,
                                                   float* __restrict__ o)
{
    const int blk  = blockIdx.x;
    const int bh   = blk >> 1;
    const int half = blk & 1;
    const int b = bh >> 4, h = bh & 15;
    const int tid = threadIdx.x;
    const int col = tid >> 2;
    const int sub = tid & 3;
    const int d   = half * 64 + col;

    __shared__ float k_s[2][128];
    __shared__ float q_s[2][128];
    __shared__ float v_s[2][64];
    __shared__ float gb_s[2][2];

    float s[32];
#pragma unroll
    for (int i = 0; i < 32; i++) s[i] = 0.f;

    const size_t xbase = (size_t)b * NL * CONVD;

    float r0 = 0.f, r1 = 0.f;
    {
        const size_t row = xbase;
        if (tid < 128) r0 = x[row + KEYD + h * 128 + tid];
        else           r0 = x[row + h * 128 + (tid - 128)];
        if (tid < 64)       r1 = x[row + 2 * KEYD + h * 128 + half * 64 + tid];
        else if (tid == 64) r1 = gg[(b * NL) * NH + h];
        else if (tid == 65) r1 = bb[(b * NL) * NH + h];
    }
    if (tid < 128) k_s[0][tid] = r0; else q_s[0][tid - 128] = r0;
    if (tid < 64)       v_s[0][tid]  = r1;
    else if (tid == 64) gb_s[0][0]   = r1;
    else if (tid == 65) gb_s[0][1]   = r1;
    __syncthreads();

    const float scale = 0.08838834764831845f;
    float* obase = o + (size_t)b * NL * VALD + h * 128 + d;

    for (int l = 0; l < NL; l++) {
        const int cur = l & 1;
        const float eg   = expf(gb_s[cur][0]);
        const float beta = gb_s[cur][1];
        const float vv   = v_s[cur][col];
        float kr[32];
#pragma unroll
        for (int i = 0; i < 32; i++) kr[i] = k_s[cur][i * 4 + sub];

        if (l + 1 < NL) {
            const size_t row = xbase + (size_t)(l + 1) * CONVD;
            if (tid < 128) r0 = x[row + KEYD + h * 128 + tid];
            else           r0 = x[row + h * 128 + (tid - 128)];
            if (tid < 64)       r1 = x[row + 2 * KEYD + h * 128 + half * 64 + tid];
            else if (tid == 64) r1 = gg[(b * NL + l + 1) * NH + h];
            else if (tid == 65) r1 = bb[(b * NL + l + 1) * NH + h];
        }

        float vp = 0.f;
#pragma unroll
        for (int i = 0; i < 32; i++) {
            s[i] *= eg;
            vp += kr[i] * s[i];
        }
        vp += __shfl_xor_sync(0xffffffffu, vp, 1);
        vp += __shfl_xor_sync(0xffffffffu, vp, 2);
        const float delta = (vv - vp) * beta;

        float oo = 0.f;
#pragma unroll
        for (int i = 0; i < 32; i++) {
            s[i] += kr[i] * delta;
            oo += q_s[cur][i * 4 + sub] * s[i];
        }
        oo += __shfl_xor_sync(0xffffffffu, oo, 1);
        oo += __shfl_xor_sync(0xffffffffu, oo, 2);
        if (sub == 0) obase[(size_t)l * VALD] = oo * scale;

        if (l + 1 < NL) {
            const int nxt = cur ^ 1;
            if (tid < 128) k_s[nxt][tid] = r0; else q_s[nxt][tid - 128] = r0;
            if (tid < 64)       v_s[nxt][tid] = r1;
            else if (tid == 64) gb_s[nxt][0]  = r1;
            else if (tid == 65) gb_s[nxt][1]  = r1;
        }
        __syncthreads();
    }
}

// ==================== RMS norm + sigmoid(z) gate ====================
__global__ void __launch_bounds__(256) gate_norm_kernel(const float* __restrict__ qkvz,
                                                        const float* __restrict__ norm_w,
                                                        float* __restrict__ o)
{
    const int gid  = blockIdx.x * 256 + threadIdx.x;
    const int wid  = gid >> 5;
    const int lane = gid & 31;
    const int bl = wid >> 4;
    const int h  = wid & 15;

    float* op = o + (size_t)bl * VALD + h * 128 + lane * 4;
    float4 ov = *(float4*)op;
    float ss = ov.x * ov.x + ov.y * ov.y + ov.z * ov.z + ov.w * ov.w;
#pragma unroll
    for (int off = 16; off; off >>= 1) ss += __shfl_xor_sync(0xffffffffu, ss, off);
    const float rs = rsqrtf(ss * (1.f / 128.f) + 1e-6f);

    const float4 z = *(const float4*)&qkvz[(size_t)bl * QKVZN + CONVD + h * 128 + lane * 4];
    const float4 w = *(const float4*)&norm_w[lane * 4];
    ov.x = ov.x * rs * w.x * (1.f / (1.f + expf(-z.x)));
    ov.y = ov.y * rs * w.y * (1.f / (1.f + expf(-z.y)));
    ov.z = ov.z * rs * w.z * (1.f / (1.f + expf(-z.z)));
    ov.w = ov.w * rs * w.w * (1.f / (1.f + expf(-z.w)));
    *(float4*)op = ov;
}

// ====================================================================
extern "C" void kernel_launch(void* const* d_in, const int* in_sizes, int n_in,
                              void* d_out, int out_size)
{
    const float* hidden  = (const float*)d_in[0];
    const float* W_qkvz  = (const float*)d_in[1];
    const float* W_ba    = (const float*)d_in[2];
    const float* conv_w  = (const float*)d_in[3];
    const float* conv_b  = (const float*)d_in[4];
    const float* A_log   = (const float*)d_in[5];
    const float* dt_bias = (const float*)d_in[6];
    const float* norm_w  = (const float*)d_in[7];
    const float* W_out   = (const float*)d_in[8];
    float* out = (float*)d_out;

    float *qkvz, *ba, *xbuf, *gbuf, *betabuf, *obuf;
    __nv_bfloat16 *hh, *hl, *wqh, *wql, *woh, *wol, *oh, *ol;
    cudaGetSymbolAddress((void**)&qkvz,    g_qkvz);
    cudaGetSymbolAddress((void**)&ba,      g_ba);
    cudaGetSymbolAddress((void**)&xbuf,    g_x);
    cudaGetSymbolAddress((void**)&gbuf,    g_g);
    cudaGetSymbolAddress((void**)&betabuf, g_beta);
    cudaGetSymbolAddress((void**)&obuf,    g_o);
    cudaGetSymbolAddress((void**)&hh,  g_hh);
    cudaGetSymbolAddress((void**)&hl,  g_hl);
    cudaGetSymbolAddress((void**)&wqh, g_wqh);
    cudaGetSymbolAddress((void**)&wql, g_wql);
    cudaGetSymbolAddress((void**)&woh, g_woh);
    cudaGetSymbolAddress((void**)&wol, g_wol);
    cudaGetSymbolAddress((void**)&oh,  g_oh);
    cudaGetSymbolAddress((void**)&ol,  g_ol);

    cudaFuncSetAttribute(mma_gemm, cudaFuncAttributeMaxDynamicSharedMemorySize, GEMM_SMEM);

    // 0. split/transpose operands to bf16 hi/lo
    split_kernel<<<(ML * HID / 4 + 255) / 256, 256>>>(hidden, hh, hl, ML * HID / 4);
    tsplit_kernel<<<dim3(QKVZN / 32, HID / 32), dim3(32, 8)>>>(W_qkvz, wqh, wql, HID, QKVZN);
    tsplit_kernel<<<dim3(HID / 32, VALD / 32), dim3(32, 8)>>>(W_out, woh, wol, VALD, HID);

    // 1. qkvz = hidden @ W_qkvz   [4096, 8192]   (mma.sync bf16, 3-product split)
    mma_gemm<<<dim3(QKVZN / BN, ML / BM), 256, GEMM_SMEM>>>(hh, hl, wqh, wql, qkvz, HID, QKVZN);
    // 2. ba = hidden @ W_ba       [4096, 32]
    ba_gemm_kernel<<<ML / 8, 256>>>(hidden, W_ba, ba);
    // 3. conv + l2norm + g/beta
    conv_norm_kernel<<<ML, 256>>>(qkvz, ba, conv_w, conv_b, A_log, dt_bias,
                                  xbuf, gbuf, betabuf);
    // 4. gated delta scan
    scan_kernel<<<128, 256>>>(xbuf, gbuf, betabuf, obuf);
    // 5. RMS norm + sigmoid(z) gate
    gate_norm_kernel<<<(ML * NH * 32) / 256, 256>>>(qkvz, norm_w, obuf);
    // 6. split o, then out = o @ W_out  [4096, 2048]
    split_kernel<<<(ML * VALD / 4 + 255) / 256, 256>>>(obuf, oh, ol, ML * VALD / 4);
    mma_gemm<<<dim3(HID / BN, ML / BM), 256, GEMM_SMEM>>>(oh, ol, woh, wol, out, VALD, HID);
}